// round 3
// baseline (speedup 1.0000x reference)
#include <cuda_runtime.h>
#include <cstdint>

// Problem constants: x (2,4,128,128,128) f32, y (2,1,128,128,128) int32
// (JAX without x64 downcasts the declared int64 to int32.)
#define SPB   (1u << 21)   // spatial voxels per batch: 128^3
#define NTOT  (1u << 22)   // total voxels: 2 * 128^3

// Scratch (device globals — no allocation allowed)
__device__ unsigned char g_flags[NTOT];  // bit0: P==1, bit1: P==3, bit2: P!=1 && P!=2
__device__ unsigned char g_tmp[NTOT];    // ping
__device__ unsigned char g_dil[NTOT];    // pong
__device__ float         g_ce[NTOT];     // per-voxel cross entropy

// ---------------------------------------------------------------------------
// K1: argmax flags + cross entropy per voxel
// ---------------------------------------------------------------------------
__global__ void k_flags_ce(const float* __restrict__ x,
                           const int* __restrict__ y) {
    unsigned i = blockIdx.x * blockDim.x + threadIdx.x;
    if (i >= NTOT) return;
    unsigned b = i >> 21;
    unsigned v = i & (SPB - 1);
    const float* xb = x + (size_t)b * 4 * SPB + v;
    float x0 = xb[0], x1 = xb[SPB], x2 = xb[2 * SPB], x3 = xb[3 * SPB];

    // argmax, first-max semantics (matches jnp.argmax)
    float best = x0; int p = 0;
    if (x1 > best) { best = x1; p = 1; }
    if (x2 > best) { best = x2; p = 2; }
    if (x3 > best) { best = x3; p = 3; }

    unsigned char f = (unsigned char)((p == 1 ? 1u : 0u) |
                                      (p == 3 ? 2u : 0u) |
                                      ((p != 1 && p != 2) ? 4u : 0u));
    g_flags[i] = f;

    float m = best;
    float lse = m + logf(expf(x0 - m) + expf(x1 - m) + expf(x2 - m) + expf(x3 - m));
    int yi = y[i];
    float xy = (yi == 0) ? x0 : (yi == 1) ? x1 : (yi == 2) ? x2 : x3;
    g_ce[i] = lse - xy;
}

// ---------------------------------------------------------------------------
// K2: dilate along x (W, contiguous). One uint32 = 4 voxels per thread.
// 128 bytes per row = 32 words; clamp at row edges.
// ---------------------------------------------------------------------------
__global__ void k_dilx(const uint32_t* __restrict__ in, uint32_t* __restrict__ out) {
    unsigned i = blockIdx.x * blockDim.x + threadIdx.x;
    if (i >= NTOT / 4) return;
    uint32_t w = in[i];
    unsigned col = i & 31u;
    uint32_t prev = (col == 0)  ? 0u : in[i - 1];
    uint32_t next = (col == 31) ? 0u : in[i + 1];
    uint32_t left  = (w << 8) | (prev >> 24);  // f[x-1] for each byte lane
    uint32_t right = (w >> 8) | (next << 24);  // f[x+1]
    out[i] = w | left | right;
}

// ---------------------------------------------------------------------------
// K3: dilate along y (stride 128 bytes = 8 uint4). One uint4 = 16 voxels.
// ---------------------------------------------------------------------------
__global__ void k_dily(const uint4* __restrict__ in, uint4* __restrict__ out) {
    unsigned i = blockIdx.x * blockDim.x + threadIdx.x;
    if (i >= NTOT / 16) return;
    unsigned yrow = (i >> 3) & 127u;   // 8 uint4 per row; y cycles every 128 rows
    uint4 c = in[i];
    uint4 r = c;
    if (yrow != 0) {
        uint4 u = in[i - 8];
        r.x |= u.x; r.y |= u.y; r.z |= u.z; r.w |= u.w;
    }
    if (yrow != 127) {
        uint4 d = in[i + 8];
        r.x |= d.x; r.y |= d.y; r.z |= d.z; r.w |= d.w;
    }
    out[i] = r;
}

// ---------------------------------------------------------------------------
// K4: dilate along z (stride 128*128 bytes = 1024 uint4). Per-batch clamp.
// ---------------------------------------------------------------------------
__global__ void k_dilz(const uint4* __restrict__ in, uint4* __restrict__ out) {
    unsigned i = blockIdx.x * blockDim.x + threadIdx.x;
    if (i >= NTOT / 16) return;
    unsigned z = (i >> 10) & 127u;     // 1024 uint4 per z-slice; 128 z per batch
    uint4 c = in[i];
    uint4 r = c;
    if (z != 0) {
        uint4 u = in[i - 1024];
        r.x |= u.x; r.y |= u.y; r.z |= u.z; r.w |= u.w;
    }
    if (z != 127) {
        uint4 d = in[i + 1024];
        r.x |= d.x; r.y |= d.y; r.z |= d.z; r.w |= d.w;
    }
    out[i] = r;
}

// ---------------------------------------------------------------------------
// K5: masked sum.  crit = (f&1 && N&6) || (f&6 && N&1)
//   interaction 1 (inclusion 1 in 2): (P==1 && N_{not12}) || (P!={1,2} && N_1)
//   interaction 2 (exclusion 1,3):    (P==1 && N_3)       || (P==3      && N_1)
// ---------------------------------------------------------------------------
__global__ void k_zero(float* out) { out[0] = 0.0f; }

__global__ void k_final(const uint4* __restrict__ flags4,
                        const uint4* __restrict__ dil4,
                        const float4* __restrict__ ce4,
                        float* __restrict__ out) {
    unsigned i = blockIdx.x * blockDim.x + threadIdx.x;
    float s = 0.0f;
    if (i < NTOT / 16) {
        uint4 f = flags4[i];
        uint4 d = dil4[i];
        unsigned fw[4] = {f.x, f.y, f.z, f.w};
        unsigned dw[4] = {d.x, d.y, d.z, d.w};
        #pragma unroll
        for (int w = 0; w < 4; w++) {
            float4 c = ce4[i * 4 + w];
            float cv[4] = {c.x, c.y, c.z, c.w};
            #pragma unroll
            for (int k = 0; k < 4; k++) {
                unsigned fb = (fw[w] >> (8 * k)) & 0xFFu;
                unsigned db = (dw[w] >> (8 * k)) & 0xFFu;
                bool crit = ((fb & 1u) && (db & 6u)) || ((fb & 6u) && (db & 1u));
                if (crit) s += cv[k];
            }
        }
    }
    // warp reduce
    #pragma unroll
    for (int o = 16; o; o >>= 1) s += __shfl_down_sync(0xFFFFFFFFu, s, o);
    __shared__ float ws[8];
    int lane = threadIdx.x & 31, warp = threadIdx.x >> 5;
    if (lane == 0) ws[warp] = s;
    __syncthreads();
    if (warp == 0) {
        s = (lane < (int)(blockDim.x >> 5)) ? ws[lane] : 0.0f;
        #pragma unroll
        for (int o = 4; o; o >>= 1) s += __shfl_down_sync(0xFFFFFFFFu, s, o);
        if (lane == 0) atomicAdd(out, 0.5f * s);  // mean over batch of 2
    }
}

// ---------------------------------------------------------------------------
extern "C" void kernel_launch(void* const* d_in, const int* in_sizes, int n_in,
                              void* d_out, int out_size) {
    const float* x = (const float*)d_in[0];
    const int*   y = (const int*)d_in[1];
    float* out = (float*)d_out;

    unsigned char *flags, *tmp, *dil;
    float* ce;
    cudaGetSymbolAddress((void**)&flags, g_flags);
    cudaGetSymbolAddress((void**)&tmp,   g_tmp);
    cudaGetSymbolAddress((void**)&dil,   g_dil);
    cudaGetSymbolAddress((void**)&ce,    g_ce);

    const int T = 256;
    k_flags_ce<<<NTOT / T, T>>>(x, y);
    k_dilx<<<(NTOT / 4) / T, T>>>((const uint32_t*)flags, (uint32_t*)tmp);
    k_dily<<<(NTOT / 16) / T, T>>>((const uint4*)tmp, (uint4*)dil);
    k_dilz<<<(NTOT / 16) / T, T>>>((const uint4*)dil, (uint4*)tmp);
    k_zero<<<1, 1>>>(out);
    k_final<<<(NTOT / 16) / T, T>>>((const uint4*)flags, (const uint4*)tmp,
                                    (const float4*)ce, out);
}

// round 4
// speedup vs baseline: 1.4528x; 1.4528x over previous
#include <cuda_runtime.h>
#include <cstdint>

// x (2,4,128,128,128) f32, y (2,1,128,128,128) int32 -> scalar f32
#define SPB   (1u << 21)   // 128^3 voxels per batch
#define NTOT  (1u << 22)   // 2 * 128^3

__device__ unsigned char g_flags[NTOT];  // raw flags: bit0 P==1, bit1 P==3, bit2 P!=1&&P!=2
__device__ unsigned char g_tmp[NTOT];    // x-dilated flags
__device__ float         g_ce[NTOT];     // per-voxel CE

// ---------------------------------------------------------------------------
// K1: argmax flags + CE + x-dilation (in shared memory), 4 voxels/thread.
// Block = 256 threads * 4 voxels = 1024 voxels = 8 complete x-rows.
// ---------------------------------------------------------------------------
__global__ void k_flags_ce_dilx(const float* __restrict__ x,
                                const int*   __restrict__ y,
                                float* __restrict__ out) {
    __shared__ uint32_t sw[256];
    unsigned t  = blockIdx.x * 256u + threadIdx.x;   // word index (4 voxels)
    unsigned i4 = t * 4u;                            // first voxel index
    unsigned b  = i4 >> 21;
    unsigned v  = i4 & (SPB - 1);
    const float* xb = x + (size_t)b * 4 * SPB + v;

    float4 a0 = *(const float4*)(xb);
    float4 a1 = *(const float4*)(xb + SPB);
    float4 a2 = *(const float4*)(xb + 2 * SPB);
    float4 a3 = *(const float4*)(xb + 3 * SPB);
    int4   yy = *(const int4*)(y + i4);

    float c0[4] = {a0.x, a0.y, a0.z, a0.w};
    float c1[4] = {a1.x, a1.y, a1.z, a1.w};
    float c2[4] = {a2.x, a2.y, a2.z, a2.w};
    float c3[4] = {a3.x, a3.y, a3.z, a3.w};
    int   yv[4] = {yy.x, yy.y, yy.z, yy.w};

    uint32_t w = 0;
    float4 ce;
    float* cep = (float*)&ce;
    #pragma unroll
    for (int j = 0; j < 4; j++) {
        float x0 = c0[j], x1 = c1[j], x2 = c2[j], x3 = c3[j];
        float best = x0; int p = 0;
        if (x1 > best) { best = x1; p = 1; }
        if (x2 > best) { best = x2; p = 2; }
        if (x3 > best) { best = x3; p = 3; }
        // lut: p=0 -> 4, p=1 -> 1, p=2 -> 0, p=3 -> 6
        unsigned f = (p == 0) ? 4u : (p == 1) ? 1u : (p == 2) ? 0u : 6u;
        w |= f << (8 * j);
        float m = best;
        float lse = m + logf(expf(x0 - m) + expf(x1 - m) + expf(x2 - m) + expf(x3 - m));
        int yi = yv[j];
        float xy = (yi == 0) ? x0 : (yi == 1) ? x1 : (yi == 2) ? x2 : x3;
        cep[j] = lse - xy;
    }

    *(uint32_t*)(g_flags + i4) = w;
    *(float4*)(g_ce + i4) = ce;
    sw[threadIdx.x] = w;
    __syncthreads();

    // x-dilation: each row = 32 words; col = position in row (rows never span blocks)
    unsigned col = threadIdx.x & 31u;
    uint32_t prev = (col == 0)  ? 0u : sw[threadIdx.x - 1];
    uint32_t next = (col == 31) ? 0u : sw[threadIdx.x + 1];
    uint32_t left  = (w << 8) | (prev >> 24);
    uint32_t right = (w >> 8) | (next << 24);
    *(uint32_t*)(g_tmp + i4) = w | left | right;

    if (t == 0) out[0] = 0.0f;
}

// ---------------------------------------------------------------------------
// K2: fused y-dilation + z-dilation (9-tap OR over x-dilated words) + masked
// CE reduction. One uint4 (16 voxels) per thread.
// index layout (uint4 units): b(1) | z(7) | y(7) | xq(3)
// ---------------------------------------------------------------------------
__global__ void k_dilyz_final(const uint4* __restrict__ tmp4,
                              const uint4* __restrict__ flags4,
                              const float4* __restrict__ ce4,
                              float* __restrict__ out) {
    unsigned i = blockIdx.x * blockDim.x + threadIdx.x;  // 0 .. NTOT/16-1
    float s = 0.0f;
    if (i < NTOT / 16) {
        unsigned yrow = (i >> 3) & 127u;
        unsigned z    = (i >> 10) & 127u;

        uint4 n = make_uint4(0, 0, 0, 0);
        #pragma unroll
        for (int dz = -1; dz <= 1; dz++) {
            if ((dz == -1 && z == 0) || (dz == 1 && z == 127)) continue;
            #pragma unroll
            for (int dy = -1; dy <= 1; dy++) {
                if ((dy == -1 && yrow == 0) || (dy == 1 && yrow == 127)) continue;
                uint4 u = tmp4[(int)i + dz * 1024 + dy * 8];
                n.x |= u.x; n.y |= u.y; n.z |= u.z; n.w |= u.w;
            }
        }

        uint4 f = flags4[i];
        unsigned fw[4] = {f.x, f.y, f.z, f.w};
        unsigned nw[4] = {n.x, n.y, n.z, n.w};
        #pragma unroll
        for (int w = 0; w < 4; w++) {
            float4 c = ce4[i * 4 + w];
            float cv[4] = {c.x, c.y, c.z, c.w};
            #pragma unroll
            for (int k = 0; k < 4; k++) {
                unsigned fb = (fw[w] >> (8 * k)) & 0xFFu;
                unsigned db = (nw[w] >> (8 * k)) & 0xFFu;
                bool crit = ((fb & 1u) && (db & 6u)) || ((fb & 6u) && (db & 1u));
                if (crit) s += cv[k];
            }
        }
    }

    // block reduce + atomic
    #pragma unroll
    for (int o = 16; o; o >>= 1) s += __shfl_down_sync(0xFFFFFFFFu, s, o);
    __shared__ float ws[8];
    int lane = threadIdx.x & 31, warp = threadIdx.x >> 5;
    if (lane == 0) ws[warp] = s;
    __syncthreads();
    if (warp == 0) {
        s = (lane < (int)(blockDim.x >> 5)) ? ws[lane] : 0.0f;
        #pragma unroll
        for (int o = 4; o; o >>= 1) s += __shfl_down_sync(0xFFFFFFFFu, s, o);
        if (lane == 0) atomicAdd(out, 0.5f * s);   // mean over batch of 2
    }
}

// ---------------------------------------------------------------------------
extern "C" void kernel_launch(void* const* d_in, const int* in_sizes, int n_in,
                              void* d_out, int out_size) {
    const float* x = (const float*)d_in[0];
    const int*   y = (const int*)d_in[1];
    float* out = (float*)d_out;

    unsigned char *flags, *tmp;
    float* ce;
    cudaGetSymbolAddress((void**)&flags, g_flags);
    cudaGetSymbolAddress((void**)&tmp,   g_tmp);
    cudaGetSymbolAddress((void**)&ce,    g_ce);

    k_flags_ce_dilx<<<NTOT / 1024, 256>>>(x, y, out);
    k_dilyz_final<<<(NTOT / 16) / 256, 256>>>((const uint4*)tmp, (const uint4*)flags,
                                              (const float4*)ce, out);
}

// round 5
// speedup vs baseline: 2.0568x; 1.4157x over previous
#include <cuda_runtime.h>
#include <cuda_fp16.h>
#include <cstdint>

// x (2,4,128,128,128) f32, y (2,1,128,128,128) int32 -> scalar f32
#define SPB    (1u << 21)       // 128^3 voxels per batch
#define NTOT   (1u << 22)       // 2 * 128^3
#define NWORDS (NTOT / 32)      // packed words (32 voxels each): 131072

// Bit-plane scratch: A = (P==1), B = (P==0 || P==3)
// crit = (A & dil3D(B)) | (B & dil3D(A))
__device__ uint32_t g_rA[NWORDS];   // raw A plane
__device__ uint32_t g_rB[NWORDS];   // raw B plane
__device__ uint32_t g_dA[NWORDS];   // x-dilated A
__device__ uint32_t g_dB[NWORDS];   // x-dilated B
__device__ uint4    g_ceh[NTOT / 8]; // per-voxel CE, fp16 (8 halves per uint4)

// ---------------------------------------------------------------------------
// K1: argmax -> bit planes (+x-dilation), CE (fp16). 4 voxels/thread.
// Block = 256 threads = 1024 voxels = 8 complete x-rows = 32 packed words.
// ---------------------------------------------------------------------------
__global__ void k1(const float* __restrict__ x,
                   const int*   __restrict__ y,
                   float* __restrict__ out) {
    __shared__ unsigned char snib[256];   // lo nibble: A bits, hi nibble: B bits

    unsigned t  = blockIdx.x * 256u + threadIdx.x;
    unsigned i4 = t * 4u;
    unsigned b  = i4 >> 21;
    unsigned v  = i4 & (SPB - 1);
    const float* xb = x + (size_t)b * 4 * SPB + v;

    float4 a0 = *(const float4*)(xb);
    float4 a1 = *(const float4*)(xb + SPB);
    float4 a2 = *(const float4*)(xb + 2 * SPB);
    float4 a3 = *(const float4*)(xb + 3 * SPB);
    int4   yy = *(const int4*)(y + i4);

    float c0[4] = {a0.x, a0.y, a0.z, a0.w};
    float c1[4] = {a1.x, a1.y, a1.z, a1.w};
    float c2[4] = {a2.x, a2.y, a2.z, a2.w};
    float c3[4] = {a3.x, a3.y, a3.z, a3.w};
    int   yv[4] = {yy.x, yy.y, yy.z, yy.w};

    unsigned nib = 0;
    float cef[4];
    #pragma unroll
    for (int j = 0; j < 4; j++) {
        float x0 = c0[j], x1 = c1[j], x2 = c2[j], x3 = c3[j];
        float best = x0; int p = 0;
        if (x1 > best) { best = x1; p = 1; }
        if (x2 > best) { best = x2; p = 2; }
        if (x3 > best) { best = x3; p = 3; }
        unsigned A = (p == 1) ? 1u : 0u;
        unsigned B = (p == 0 || p == 3) ? 1u : 0u;
        nib |= (A << j) | (B << (j + 4));
        float m = best;
        float lse = m + __logf(__expf(x0 - m) + __expf(x1 - m) +
                               __expf(x2 - m) + __expf(x3 - m));
        int yi = yv[j];
        float xy = (yi == 0) ? x0 : (yi == 1) ? x1 : (yi == 2) ? x2 : x3;
        cef[j] = lse - xy;
    }

    // fp16 CE, 4 halves = 8 bytes per thread
    __half2 h01 = __floats2half2_rn(cef[0], cef[1]);
    __half2 h23 = __floats2half2_rn(cef[2], cef[3]);
    uint2 cw;
    cw.x = *(const unsigned*)&h01;
    cw.y = *(const unsigned*)&h23;
    ((uint2*)g_ceh)[t] = cw;

    snib[threadIdx.x] = (unsigned char)nib;
    __syncthreads();

    // Warp 0 assembles 32 words (one per lane), x-dilates, writes planes.
    if (threadIdx.x < 32) {
        unsigned w = threadIdx.x;
        uint32_t wA = 0, wB = 0;
        #pragma unroll
        for (int j = 0; j < 8; j++) {
            unsigned n = snib[w * 8 + j];
            wA |= (n & 0xFu) << (4 * j);
            wB |= (n >> 4)   << (4 * j);
        }
        // neighbor words live in adjacent lanes; clamp at row edges (4 words/row)
        uint32_t pA = __shfl_up_sync(0xFFFFFFFFu, wA, 1);
        uint32_t nAx = __shfl_down_sync(0xFFFFFFFFu, wA, 1);
        uint32_t pB = __shfl_up_sync(0xFFFFFFFFu, wB, 1);
        uint32_t nBx = __shfl_down_sync(0xFFFFFFFFu, wB, 1);
        if ((w & 3u) == 0) { pA = 0; pB = 0; }
        if ((w & 3u) == 3) { nAx = 0; nBx = 0; }
        uint32_t dA = wA | (wA << 1) | (pA >> 31) | (wA >> 1) | (nAx << 31);
        uint32_t dB = wB | (wB << 1) | (pB >> 31) | (wB >> 1) | (nBx << 31);

        unsigned gw = blockIdx.x * 32u + w;
        g_rA[gw] = wA;
        g_rB[gw] = wB;
        g_dA[gw] = dA;
        g_dB[gw] = dB;
    }

    if (t == 0) out[0] = 0.0f;
}

// ---------------------------------------------------------------------------
// K2: 9-tap (y,z) OR over x-dilated planes -> crit word -> masked CE sum.
// One packed word (32 voxels) per thread.
// word layout: b(1) | z(7) | y(7) | wx(2)
// ---------------------------------------------------------------------------
__global__ void k2(float* __restrict__ out) {
    unsigned wi = blockIdx.x * blockDim.x + threadIdx.x;   // < NWORDS
    float s = 0.0f;

    unsigned yr = (wi >> 2) & 127u;
    unsigned z  = (wi >> 9) & 127u;

    uint32_t nA = 0, nB = 0;
    #pragma unroll
    for (int dz = -1; dz <= 1; dz++) {
        if ((dz == -1 && z == 0) || (dz == 1 && z == 127)) continue;
        #pragma unroll
        for (int dy = -1; dy <= 1; dy++) {
            if ((dy == -1 && yr == 0) || (dy == 1 && yr == 127)) continue;
            int idx = (int)wi + dz * 512 + dy * 4;
            nA |= g_dA[idx];
            nB |= g_dB[idx];
        }
    }

    uint32_t crit = (g_rA[wi] & nB) | (g_rB[wi] & nA);

    if (crit) {
        // 32 fp16 CE values = 64 bytes = 4 uint4
        const uint4* cep = &g_ceh[wi * 4];
        #pragma unroll
        for (int q = 0; q < 4; q++) {
            uint4 c = cep[q];
            unsigned hw[4] = {c.x, c.y, c.z, c.w};
            #pragma unroll
            for (int j = 0; j < 4; j++) {
                float2 f2 = __half22float2(*(const __half2*)&hw[j]);
                unsigned base = q * 8 + j * 2;
                if ((crit >> base) & 1u)       s += f2.x;
                if ((crit >> (base + 1)) & 1u) s += f2.y;
            }
        }
    }

    // block reduce + atomic
    #pragma unroll
    for (int o = 16; o; o >>= 1) s += __shfl_down_sync(0xFFFFFFFFu, s, o);
    __shared__ float ws[8];
    int lane = threadIdx.x & 31, warp = threadIdx.x >> 5;
    if (lane == 0) ws[warp] = s;
    __syncthreads();
    if (warp == 0) {
        s = (lane < (int)(blockDim.x >> 5)) ? ws[lane] : 0.0f;
        #pragma unroll
        for (int o = 4; o; o >>= 1) s += __shfl_down_sync(0xFFFFFFFFu, s, o);
        if (lane == 0) atomicAdd(out, 0.5f * s);   // mean over batch of 2
    }
}

// ---------------------------------------------------------------------------
extern "C" void kernel_launch(void* const* d_in, const int* in_sizes, int n_in,
                              void* d_out, int out_size) {
    const float* x = (const float*)d_in[0];
    const int*   y = (const int*)d_in[1];
    float* out = (float*)d_out;

    k1<<<NTOT / 1024, 256>>>(x, y, out);
    k2<<<NWORDS / 256, 256>>>(out);
}

// round 6
// speedup vs baseline: 2.0846x; 1.0135x over previous
#include <cuda_runtime.h>
#include <cuda_fp16.h>
#include <cstdint>

// x (2,4,128,128,128) f32, y (2,1,128,128,128) int32 -> scalar f32
#define SPB    (1u << 21)       // 128^3 voxels per batch
#define NTOT   (1u << 22)       // 2 * 128^3
#define NWORDS (NTOT / 32)      // packed words (32 voxels each): 131072

// Bit-plane scratch, interleaved: .x = A-plane (P==1), .y = B-plane (P in {0,3})
// crit = (rA & dil3D(B)) | (rB & dil3D(A))
__device__ uint2 g_rAB[NWORDS];     // raw planes
__device__ uint2 g_dAB[NWORDS];     // x-dilated planes
__device__ uint4 g_ceh[NTOT / 8];   // per-voxel CE, fp16 (8 halves per uint4)

// ---------------------------------------------------------------------------
// K1: argmax -> bit planes (+x-dilation), CE (fp16). 4 voxels/thread.
// Block = 256 threads = 1024 voxels = 8 complete x-rows = 32 packed words.
// ---------------------------------------------------------------------------
__global__ void k1(const float* __restrict__ x,
                   const int*   __restrict__ y,
                   float* __restrict__ out) {
    __shared__ unsigned char snib[256];   // lo nibble: A bits, hi nibble: B bits

    unsigned t  = blockIdx.x * 256u + threadIdx.x;
    unsigned i4 = t * 4u;
    unsigned b  = i4 >> 21;
    unsigned v  = i4 & (SPB - 1);
    const float* xb = x + (size_t)b * 4 * SPB + v;

    float4 a0 = *(const float4*)(xb);
    float4 a1 = *(const float4*)(xb + SPB);
    float4 a2 = *(const float4*)(xb + 2 * SPB);
    float4 a3 = *(const float4*)(xb + 3 * SPB);
    int4   yy = *(const int4*)(y + i4);

    float c0[4] = {a0.x, a0.y, a0.z, a0.w};
    float c1[4] = {a1.x, a1.y, a1.z, a1.w};
    float c2[4] = {a2.x, a2.y, a2.z, a2.w};
    float c3[4] = {a3.x, a3.y, a3.z, a3.w};
    int   yv[4] = {yy.x, yy.y, yy.z, yy.w};

    unsigned nib = 0;
    float cef[4];
    #pragma unroll
    for (int j = 0; j < 4; j++) {
        float x0 = c0[j], x1 = c1[j], x2 = c2[j], x3 = c3[j];
        float best = x0; int p = 0;
        if (x1 > best) { best = x1; p = 1; }
        if (x2 > best) { best = x2; p = 2; }
        if (x3 > best) { best = x3; p = 3; }
        unsigned A = (p == 1) ? 1u : 0u;
        unsigned B = (p == 0 || p == 3) ? 1u : 0u;
        nib |= (A << j) | (B << (j + 4));
        float m = best;
        float lse = m + __logf(__expf(x0 - m) + __expf(x1 - m) +
                               __expf(x2 - m) + __expf(x3 - m));
        int yi = yv[j];
        float xy = (yi == 0) ? x0 : (yi == 1) ? x1 : (yi == 2) ? x2 : x3;
        cef[j] = lse - xy;
    }

    // fp16 CE, 4 halves = 8 bytes per thread
    __half2 h01 = __floats2half2_rn(cef[0], cef[1]);
    __half2 h23 = __floats2half2_rn(cef[2], cef[3]);
    uint2 cw;
    cw.x = *(const unsigned*)&h01;
    cw.y = *(const unsigned*)&h23;
    ((uint2*)g_ceh)[t] = cw;

    snib[threadIdx.x] = (unsigned char)nib;
    __syncthreads();

    // Warp 0 assembles 32 words (one per lane), x-dilates, writes planes.
    if (threadIdx.x < 32) {
        unsigned w = threadIdx.x;
        uint32_t wA = 0, wB = 0;
        #pragma unroll
        for (int j = 0; j < 8; j++) {
            unsigned n = snib[w * 8 + j];
            wA |= (n & 0xFu) << (4 * j);
            wB |= (n >> 4)   << (4 * j);
        }
        // neighbor words live in adjacent lanes; clamp at row edges (4 words/row)
        uint32_t pA  = __shfl_up_sync(0xFFFFFFFFu, wA, 1);
        uint32_t nAx = __shfl_down_sync(0xFFFFFFFFu, wA, 1);
        uint32_t pB  = __shfl_up_sync(0xFFFFFFFFu, wB, 1);
        uint32_t nBx = __shfl_down_sync(0xFFFFFFFFu, wB, 1);
        if ((w & 3u) == 0) { pA = 0; pB = 0; }
        if ((w & 3u) == 3) { nAx = 0; nBx = 0; }
        uint32_t dA = wA | (wA << 1) | (pA >> 31) | (wA >> 1) | (nAx << 31);
        uint32_t dB = wB | (wB << 1) | (pB >> 31) | (wB >> 1) | (nBx << 31);

        unsigned gw = blockIdx.x * 32u + w;
        g_rAB[gw] = make_uint2(wA, wB);
        g_dAB[gw] = make_uint2(dA, dB);
    }

    if (t == 0) out[0] = 0.0f;
}

// ---------------------------------------------------------------------------
// K2: 9-tap (y,z) OR over x-dilated planes -> crit word -> masked CE sum.
// One packed word (32 voxels) per thread; 128-thread blocks (grid 1024).
// word layout: b(1) | z(7) | y(7) | wx(2)
// CE is prefetched unconditionally (crit ~75% dense) to overlap with taps.
// ---------------------------------------------------------------------------
__global__ void k2(float* __restrict__ out) {
    unsigned wi = blockIdx.x * 128u + threadIdx.x;   // < NWORDS
    unsigned yr = (wi >> 2) & 127u;
    unsigned z  = (wi >> 9) & 127u;

    // prefetch CE (4x uint4 = 64B) — independent of the taps
    const uint4* cep = &g_ceh[wi * 4u];
    uint4 cq0 = cep[0], cq1 = cep[1], cq2 = cep[2], cq3 = cep[3];
    uint2 r = g_rAB[wi];

    uint32_t nA = 0, nB = 0;
    #pragma unroll
    for (int dz = -1; dz <= 1; dz++) {
        if ((dz == -1 && z == 0) || (dz == 1 && z == 127)) continue;
        #pragma unroll
        for (int dy = -1; dy <= 1; dy++) {
            if ((dy == -1 && yr == 0) || (dy == 1 && yr == 127)) continue;
            uint2 u = g_dAB[(int)wi + dz * 512 + dy * 4];
            nA |= u.x; nB |= u.y;
        }
    }

    uint32_t crit = (r.x & nB) | (r.y & nA);

    float s = 0.0f;
    {
        unsigned hw[8] = {cq0.x, cq0.y, cq0.z, cq0.w, cq1.x, cq1.y, cq1.z, cq1.w};
        unsigned hw2[8] = {cq2.x, cq2.y, cq2.z, cq2.w, cq3.x, cq3.y, cq3.z, cq3.w};
        #pragma unroll
        for (int j = 0; j < 8; j++) {
            float2 f2 = __half22float2(*(const __half2*)&hw[j]);
            if (crit & (1u << (2 * j)))     s += f2.x;
            if (crit & (2u << (2 * j)))     s += f2.y;
        }
        #pragma unroll
        for (int j = 0; j < 8; j++) {
            float2 f2 = __half22float2(*(const __half2*)&hw2[j]);
            if (crit & (1u << (16 + 2 * j))) s += f2.x;
            if (crit & (2u << (16 + 2 * j))) s += f2.y;
        }
    }

    // block reduce (4 warps) + atomic
    #pragma unroll
    for (int o = 16; o; o >>= 1) s += __shfl_down_sync(0xFFFFFFFFu, s, o);
    __shared__ float ws[4];
    int lane = threadIdx.x & 31, warp = threadIdx.x >> 5;
    if (lane == 0) ws[warp] = s;
    __syncthreads();
    if (warp == 0) {
        s = (lane < 4) ? ws[lane] : 0.0f;
        #pragma unroll
        for (int o = 2; o; o >>= 1) s += __shfl_down_sync(0xFFFFFFFFu, s, o);
        if (lane == 0) atomicAdd(out, 0.5f * s);   // mean over batch of 2
    }
}

// ---------------------------------------------------------------------------
extern "C" void kernel_launch(void* const* d_in, const int* in_sizes, int n_in,
                              void* d_out, int out_size) {
    const float* x = (const float*)d_in[0];
    const int*   y = (const int*)d_in[1];
    float* out = (float*)d_out;

    k1<<<NTOT / 1024, 256>>>(x, y, out);
    k2<<<NWORDS / 128, 128>>>(out);
}